// round 1
// baseline (speedup 1.0000x reference)
#include <cuda_runtime.h>
#include <math.h>

#define B_ 4
#define T_ 2048
#define C_ 1024
#define H_ 16
#define D_ 64
#define R_ 64
#define NT 8192   // B*T

// ---------------- scratch (device globals; no allocation) ----------------
__device__ float g_P[NT * R_];     // 2 MB   rank-space intermediate
__device__ float g_Q[NT * C_];     // 32 MB  [B,H,T,D]
__device__ float g_K[NT * C_];     // 32 MB
__device__ float g_V[NT * C_];     // 32 MB
__device__ float g_Y[NT * C_];     // 32 MB  attention out, [B,T,C]

// ---------------------------------------------------------------------------
// K1: P = (A @ V^T) * s      A:[NT,C] row-major, V:[R,C] row-major, P:[NT,R]
// block = 64 rows x 64 cols (full R), 256 threads, 4x4 microtile, BK=32
// ---------------------------------------------------------------------------
__global__ __launch_bounds__(256) void k_xv(const float* __restrict__ Ain,
                                            const float* __restrict__ Vw,
                                            int useY) {
    __shared__ float As[64][33];
    __shared__ float Bs[32][68];
    const float* A = useY ? g_Y : Ain;
    const int tid = threadIdx.x, tx = tid & 15, ty = tid >> 4;
    const int tx4 = tx * 4, ty4 = ty * 4;
    const int m0 = blockIdx.x * 64;

    float acc[4][4] = {};
    for (int k0 = 0; k0 < C_; k0 += 32) {
        #pragma unroll
        for (int i = tid; i < 64 * 32; i += 256) {
            int r = i >> 5, c = i & 31;
            As[r][c] = A[(size_t)(m0 + r) * C_ + k0 + c];
        }
        #pragma unroll
        for (int i = tid; i < 64 * 32; i += 256) {
            int n = i >> 5, kk = i & 31;
            Bs[kk][n] = Vw[(size_t)n * C_ + k0 + kk];
        }
        __syncthreads();
        #pragma unroll
        for (int kk = 0; kk < 32; kk++) {
            float a[4];
            #pragma unroll
            for (int ii = 0; ii < 4; ii++) a[ii] = As[ty4 + ii][kk];
            const float4 bv = *(const float4*)&Bs[kk][tx4];
            const float b[4] = {bv.x, bv.y, bv.z, bv.w};
            #pragma unroll
            for (int ii = 0; ii < 4; ii++)
                #pragma unroll
                for (int jj = 0; jj < 4; jj++)
                    acc[ii][jj] = fmaf(a[ii], b[jj], acc[ii][jj]);
        }
        __syncthreads();
    }
    // harmonic scale s_n = (n+1)^(-0.7), applied on the R (output-col) axis
    float s[4];
    #pragma unroll
    for (int jj = 0; jj < 4; jj++) s[jj] = powf((float)(tx4 + jj + 1), -0.7f);
    #pragma unroll
    for (int ii = 0; ii < 4; ii++) {
        float4 o = make_float4(acc[ii][0] * s[0], acc[ii][1] * s[1],
                               acc[ii][2] * s[2], acc[ii][3] * s[3]);
        *(float4*)&g_P[(size_t)(m0 + ty4 + ii) * R_ + tx4] = o;
    }
}

// ---------------------------------------------------------------------------
// K2: out = P @ U^T           P:[NT,R], U:[C,R] row-major
// sel 0/1/2 -> g_Q/g_K/g_V with head-split [B,H,T,D]; sel 3 -> flat [NT,C]
// block = 64x64 tile, 256 threads, 4x4 microtile, K=64 single chunk
// ---------------------------------------------------------------------------
__global__ __launch_bounds__(256) void k_pu(const float* __restrict__ U,
                                            float* __restrict__ outp,
                                            int sel) {
    __shared__ float As[64][65];
    __shared__ float Bs[64][68];
    const int tid = threadIdx.x, tx = tid & 15, ty = tid >> 4;
    const int tx4 = tx * 4, ty4 = ty * 4;
    const int m0 = blockIdx.y * 64, n0 = blockIdx.x * 64;

    #pragma unroll
    for (int i = tid; i < 64 * 64; i += 256) {
        int r = i >> 6, c = i & 63;
        As[r][c] = g_P[(size_t)(m0 + r) * R_ + c];
    }
    #pragma unroll
    for (int i = tid; i < 64 * 64; i += 256) {
        int n = i >> 6, r = i & 63;
        Bs[r][n] = U[(size_t)(n0 + n) * R_ + r];
    }
    __syncthreads();

    float acc[4][4] = {};
    #pragma unroll
    for (int r = 0; r < 64; r++) {
        float a[4];
        #pragma unroll
        for (int ii = 0; ii < 4; ii++) a[ii] = As[ty4 + ii][r];
        const float4 bv = *(const float4*)&Bs[r][tx4];
        const float b[4] = {bv.x, bv.y, bv.z, bv.w};
        #pragma unroll
        for (int ii = 0; ii < 4; ii++)
            #pragma unroll
            for (int jj = 0; jj < 4; jj++)
                acc[ii][jj] = fmaf(a[ii], b[jj], acc[ii][jj]);
    }

    float* out = (sel == 0) ? g_Q : (sel == 1) ? g_K : (sel == 2) ? g_V : outp;
    if (sel < 3) {
        const int h = n0 >> 6;       // tile spans exactly one head
        #pragma unroll
        for (int ii = 0; ii < 4; ii++) {
            int m = m0 + ty4 + ii;
            int b = m >> 11, t = m & (T_ - 1);
            float4 o = make_float4(acc[ii][0], acc[ii][1], acc[ii][2], acc[ii][3]);
            *(float4*)&out[(((size_t)(b * H_ + h) * T_ + t) * D_) + tx4] = o;
        }
    } else {
        #pragma unroll
        for (int ii = 0; ii < 4; ii++) {
            float4 o = make_float4(acc[ii][0], acc[ii][1], acc[ii][2], acc[ii][3]);
            *(float4*)&out[(size_t)(m0 + ty4 + ii) * C_ + n0 + tx4] = o;
        }
    }
}

// ---------------------------------------------------------------------------
// K3: causal flash attention, fp32.
// Block: 64 q-rows x full D=64, streams 64-key tiles j<=qtile.
// SMEM: Qs (transposed+swizzled), KP (K-transposed / P union, swizzled), Vs.
// Swizzle f(r)=r&28 keeps float4 contiguity -> conflict-free inner LDS.
// ---------------------------------------------------------------------------
__device__ __forceinline__ int SWZ(int r, int c) {
    return (r << 6) + (c ^ (r & 28));
}

__global__ __launch_bounds__(256) void k_attn() {
    __shared__ float Qs[64 * 64];
    __shared__ float KP[64 * 64];
    __shared__ float Vs[64 * 64];
    const int tid = threadIdx.x, tx = tid & 15, ty = tid >> 4;
    const int tx4 = tx * 4, ty4 = ty * 4;
    const int bh = blockIdx.y;
    const int qt = gridDim.x - 1 - blockIdx.x;   // heavy tiles first
    const int q0 = qt * 64;
    const float* Qb = g_Q + (size_t)bh * T_ * D_;
    const float* Kb = g_K + (size_t)bh * T_ * D_;
    const float* Vb = g_V + (size_t)bh * T_ * D_;

    // load Q tile transposed+swizzled, pre-scaled by 1/sqrt(D)=0.125
    #pragma unroll
    for (int i = tid; i < 64 * 64; i += 256) {
        int r = i >> 6, d = i & 63;
        Qs[SWZ(d, r)] = Qb[(size_t)(q0 + r) * D_ + d] * 0.125f;
    }

    float O[4][4] = {};
    float m_i[4] = {-1e30f, -1e30f, -1e30f, -1e30f};
    float l_i[4] = {0.f, 0.f, 0.f, 0.f};

    const int ntile = qt + 1;
    for (int jt = 0; jt < ntile; jt++) {
        const int kk0 = jt * 64;
        __syncthreads();   // prev-iter KP/Vs readers done (no-op on iter 0)
        #pragma unroll
        for (int i = tid; i < 64 * 64; i += 256) {
            int r = i >> 6, d = i & 63;
            KP[SWZ(d, r)] = Kb[(size_t)(kk0 + r) * D_ + d];
            Vs[r * 64 + d] = Vb[(size_t)(kk0 + r) * D_ + d];
        }
        __syncthreads();   // also covers the Qs load on iter 0

        // S = (Q*scale) @ K^T   (4x4 per thread)
        float S[4][4] = {};
        #pragma unroll
        for (int d = 0; d < 64; d++) {
            const float4 av = *(const float4*)&Qs[SWZ(d, ty4)];
            const float4 bv = *(const float4*)&KP[SWZ(d, tx4)];
            const float a[4] = {av.x, av.y, av.z, av.w};
            const float b[4] = {bv.x, bv.y, bv.z, bv.w};
            #pragma unroll
            for (int ii = 0; ii < 4; ii++)
                #pragma unroll
                for (int jj = 0; jj < 4; jj++)
                    S[ii][jj] = fmaf(a[ii], b[jj], S[ii][jj]);
        }
        __syncthreads();   // everyone done reading KP as K

        if (jt == qt) {    // diagonal tile: mask key > query (kk0 == q0 here)
            #pragma unroll
            for (int ii = 0; ii < 4; ii++)
                #pragma unroll
                for (int jj = 0; jj < 4; jj++)
                    if (tx4 + jj > ty4 + ii) S[ii][jj] = -1e30f;
        }

        // online softmax per row; row = 16 lanes (tx) -> width-16 shfl reduce
        #pragma unroll
        for (int ii = 0; ii < 4; ii++) {
            float mx = fmaxf(fmaxf(S[ii][0], S[ii][1]), fmaxf(S[ii][2], S[ii][3]));
            #pragma unroll
            for (int off = 8; off > 0; off >>= 1)
                mx = fmaxf(mx, __shfl_xor_sync(0xffffffffu, mx, off, 16));
            const float mnew = fmaxf(m_i[ii], mx);
            const float corr = __expf(m_i[ii] - mnew);
            m_i[ii] = mnew;
            float p[4], rs = 0.f;
            #pragma unroll
            for (int jj = 0; jj < 4; jj++) {
                p[jj] = __expf(S[ii][jj] - mnew);
                rs += p[jj];
            }
            #pragma unroll
            for (int off = 8; off > 0; off >>= 1)
                rs += __shfl_xor_sync(0xffffffffu, rs, off, 16);
            l_i[ii] = l_i[ii] * corr + rs;
            #pragma unroll
            for (int dd = 0; dd < 4; dd++) O[ii][dd] *= corr;
            #pragma unroll
            for (int jj = 0; jj < 4; jj++)
                KP[SWZ(tx4 + jj, ty4 + ii)] = p[jj];   // Pt[j][i]
        }
        __syncthreads();   // P visible

        // O += P @ V
        #pragma unroll
        for (int j = 0; j < 64; j++) {
            const float4 av = *(const float4*)&KP[SWZ(j, ty4)];
            const float4 bv = *(const float4*)&Vs[j * 64 + tx4];
            const float a[4] = {av.x, av.y, av.z, av.w};
            const float b[4] = {bv.x, bv.y, bv.z, bv.w};
            #pragma unroll
            for (int ii = 0; ii < 4; ii++)
                #pragma unroll
                for (int dd = 0; dd < 4; dd++)
                    O[ii][dd] = fmaf(a[ii], b[dd], O[ii][dd]);
        }
    }

    // epilogue: normalize, merge heads -> g_Y [B,T,C]
    const int b = bh >> 4, h = bh & 15;
    #pragma unroll
    for (int ii = 0; ii < 4; ii++) {
        const float inv = 1.0f / l_i[ii];
        const int q = q0 + ty4 + ii;
        float4 o = make_float4(O[ii][0] * inv, O[ii][1] * inv,
                               O[ii][2] * inv, O[ii][3] * inv);
        *(float4*)&g_Y[((size_t)b * T_ + q) * C_ + h * 64 + tx4] = o;
    }
}

// ---------------------------------------------------------------------------
extern "C" void kernel_launch(void* const* d_in, const int* in_sizes, int n_in,
                              void* d_out, int out_size) {
    (void)in_sizes; (void)n_in; (void)out_size;
    const float* x  = (const float*)d_in[0];
    const float* qU = (const float*)d_in[1];
    const float* qV = (const float*)d_in[2];
    const float* kU = (const float*)d_in[3];
    const float* kV = (const float*)d_in[4];
    const float* vU = (const float*)d_in[5];
    const float* vV = (const float*)d_in[6];
    const float* cU = (const float*)d_in[7];
    const float* cV = (const float*)d_in[8];
    float* out = (float*)d_out;

    const dim3 thr(256);
    const dim3 g_gemm1(NT / 64);            // 128
    const dim3 g_gemm2(C_ / 64, NT / 64);   // 16 x 128
    const dim3 g_att(T_ / 64, B_ * H_);     // 32 x 64

    // Q
    k_xv<<<g_gemm1, thr>>>(x, qV, 0);
    k_pu<<<g_gemm2, thr>>>(qU, nullptr, 0);
    // K
    k_xv<<<g_gemm1, thr>>>(x, kV, 0);
    k_pu<<<g_gemm2, thr>>>(kU, nullptr, 1);
    // V
    k_xv<<<g_gemm1, thr>>>(x, vV, 0);
    k_pu<<<g_gemm2, thr>>>(vU, nullptr, 2);
    // attention -> g_Y
    k_attn<<<g_att, thr>>>();
    // output projection -> d_out
    k_xv<<<g_gemm1, thr>>>(nullptr, cV, 1);
    k_pu<<<g_gemm2, thr>>>(cU, out, 3);
}

// round 3
// speedup vs baseline: 1.9340x; 1.9340x over previous
#include <cuda_runtime.h>
#include <cstdint>
#include <math.h>

#define B_ 4
#define T_ 2048
#define C_ 1024
#define H_ 16
#define D_ 64
#define R_ 64
#define NT 8192   // B*T

// ---------------- scratch (device globals; no allocation) ----------------
__device__ float g_P[NT * R_];     // 2 MB   rank-space intermediate
__device__ float g_Q[NT * C_];     // 32 MB  [B,H,T,D]
__device__ float g_K[NT * C_];     // 32 MB
__device__ float g_V[NT * C_];     // 32 MB
__device__ float g_Y[NT * C_];     // 32 MB  attention out, [B,T,C]

// =================== portable tensor-core helpers (sm_80+) =================
__device__ __forceinline__ uint32_t tf32b(float x) {
    uint32_t u;
    asm("cvt.rna.tf32.f32 %0, %1;" : "=r"(u) : "f"(x));
    return u;
}
__device__ __forceinline__ float ex2(float x) {
    float y;
    asm("ex2.approx.f32 %0, %1;" : "=f"(y) : "f"(x));
    return y;
}
__device__ __forceinline__ void mma_tf32(float* d, const uint32_t* a,
                                         uint32_t b0, uint32_t b1) {
    asm volatile(
        "mma.sync.aligned.m16n8k8.row.col.f32.tf32.tf32.f32 "
        "{%0,%1,%2,%3}, {%4,%5,%6,%7}, {%8,%9}, {%0,%1,%2,%3};"
        : "+f"(d[0]), "+f"(d[1]), "+f"(d[2]), "+f"(d[3])
        : "r"(a[0]), "r"(a[1]), "r"(a[2]), "r"(a[3]), "r"(b0), "r"(b1));
}

// ---------------------------------------------------------------------------
// K1: P = (A @ V^T) * s    (SIMT)
// ---------------------------------------------------------------------------
__global__ __launch_bounds__(256) void k_xv(const float* __restrict__ Ain,
                                            const float* __restrict__ Vw,
                                            int useY) {
    __shared__ float As[64][33];
    __shared__ float Bs[32][68];
    const float* A = useY ? g_Y : Ain;
    const int tid = threadIdx.x, tx = tid & 15, ty = tid >> 4;
    const int tx4 = tx * 4, ty4 = ty * 4;
    const int m0 = blockIdx.x * 64;

    float acc[4][4] = {};
    for (int k0 = 0; k0 < C_; k0 += 32) {
        #pragma unroll
        for (int i = tid; i < 64 * 32; i += 256) {
            int r = i >> 5, c = i & 31;
            As[r][c] = A[(size_t)(m0 + r) * C_ + k0 + c];
        }
        #pragma unroll
        for (int i = tid; i < 64 * 32; i += 256) {
            int n = i >> 5, kk = i & 31;
            Bs[kk][n] = Vw[(size_t)n * C_ + k0 + kk];
        }
        __syncthreads();
        #pragma unroll
        for (int kk = 0; kk < 32; kk++) {
            float a[4];
            #pragma unroll
            for (int ii = 0; ii < 4; ii++) a[ii] = As[ty4 + ii][kk];
            const float4 bv = *(const float4*)&Bs[kk][tx4];
            const float b[4] = {bv.x, bv.y, bv.z, bv.w};
            #pragma unroll
            for (int ii = 0; ii < 4; ii++)
                #pragma unroll
                for (int jj = 0; jj < 4; jj++)
                    acc[ii][jj] = fmaf(a[ii], b[jj], acc[ii][jj]);
        }
        __syncthreads();
    }
    float s[4];
    #pragma unroll
    for (int jj = 0; jj < 4; jj++) s[jj] = powf((float)(tx4 + jj + 1), -0.7f);
    #pragma unroll
    for (int ii = 0; ii < 4; ii++) {
        float4 o = make_float4(acc[ii][0] * s[0], acc[ii][1] * s[1],
                               acc[ii][2] * s[2], acc[ii][3] * s[3]);
        *(float4*)&g_P[(size_t)(m0 + ty4 + ii) * R_ + tx4] = o;
    }
}

// ---------------------------------------------------------------------------
// K2: out = P @ U^T   (SIMT)
// ---------------------------------------------------------------------------
__global__ __launch_bounds__(256) void k_pu(const float* __restrict__ U,
                                            float* __restrict__ outp,
                                            int sel) {
    __shared__ float As[64][65];
    __shared__ float Bs[64][68];
    const int tid = threadIdx.x, tx = tid & 15, ty = tid >> 4;
    const int tx4 = tx * 4, ty4 = ty * 4;
    const int m0 = blockIdx.y * 64, n0 = blockIdx.x * 64;

    #pragma unroll
    for (int i = tid; i < 64 * 64; i += 256) {
        int r = i >> 6, c = i & 63;
        As[r][c] = g_P[(size_t)(m0 + r) * R_ + c];
    }
    #pragma unroll
    for (int i = tid; i < 64 * 64; i += 256) {
        int n = i >> 6, r = i & 63;
        Bs[r][n] = U[(size_t)(n0 + n) * R_ + r];
    }
    __syncthreads();

    float acc[4][4] = {};
    #pragma unroll
    for (int r = 0; r < 64; r++) {
        float a[4];
        #pragma unroll
        for (int ii = 0; ii < 4; ii++) a[ii] = As[ty4 + ii][r];
        const float4 bv = *(const float4*)&Bs[r][tx4];
        const float b[4] = {bv.x, bv.y, bv.z, bv.w};
        #pragma unroll
        for (int ii = 0; ii < 4; ii++)
            #pragma unroll
            for (int jj = 0; jj < 4; jj++)
                acc[ii][jj] = fmaf(a[ii], b[jj], acc[ii][jj]);
    }

    float* out = (sel == 0) ? g_Q : (sel == 1) ? g_K : (sel == 2) ? g_V : outp;
    if (sel < 3) {
        const int h = n0 >> 6;
        #pragma unroll
        for (int ii = 0; ii < 4; ii++) {
            int m = m0 + ty4 + ii;
            int b = m >> 11, t = m & (T_ - 1);
            float4 o = make_float4(acc[ii][0], acc[ii][1], acc[ii][2], acc[ii][3]);
            *(float4*)&out[(((size_t)(b * H_ + h) * T_ + t) * D_) + tx4] = o;
        }
    } else {
        #pragma unroll
        for (int ii = 0; ii < 4; ii++) {
            float4 o = make_float4(acc[ii][0], acc[ii][1], acc[ii][2], acc[ii][3]);
            *(float4*)&out[(size_t)(m0 + ty4 + ii) * C_ + n0 + tx4] = o;
        }
    }
}

// ---------------------------------------------------------------------------
// K3: causal flash attention via mma.sync tf32 (portable HMMA path).
// 128 q-rows/CTA, 8 warps x 16 rows, 64-key tiles.
// No online max (|S| << 1 => plain exp is exact softmax): O accumulates in
// registers, single normalize at the end. exp folded to ex2 via Q pre-scale.
// ---------------------------------------------------------------------------
#define PADK 68

__global__ __launch_bounds__(256) void k_attn_mma() {
    extern __shared__ float sm[];
    float* Ks = sm;                         // [64][PADK]
    float* Vs = sm + 64 * PADK;             // [64][PADK]
    float* Pb = sm + 2 * 64 * PADK;         // 8 x [16][PADK] per-warp P
    const int tid = threadIdx.x, w = tid >> 5, lane = tid & 31;
    const int quad = lane >> 2, qc = lane & 3;
    const int bh = blockIdx.y;
    const int qt = gridDim.x - 1 - blockIdx.x;   // heavy tiles first
    const int q0 = qt * 128;
    const float* Qb = g_Q + (size_t)bh * T_ * D_;
    const float* Kb = g_K + (size_t)bh * T_ * D_;
    const float* Vb = g_V + (size_t)bh * T_ * D_;
    float* Pw = Pb + w * 16 * PADK;

    // ---- stage this warp's 16 Q rows, scaled by 0.125*log2(e), as tf32 ----
    const float qscale = 0.125f * 1.4426950408889634f;
    for (int i = lane; i < 16 * 16; i += 32) {
        int r = i >> 4, c4 = (i & 15) << 2;
        float4 v = *(const float4*)(Qb + (size_t)(q0 + w * 16 + r) * D_ + c4);
        float* dst = Pw + r * PADK + c4;
        dst[0] = __uint_as_float(tf32b(v.x * qscale));
        dst[1] = __uint_as_float(tf32b(v.y * qscale));
        dst[2] = __uint_as_float(tf32b(v.z * qscale));
        dst[3] = __uint_as_float(tf32b(v.w * qscale));
    }
    __syncwarp();

    uint32_t qa[8][4];
    #pragma unroll
    for (int kb = 0; kb < 8; kb++) {
        const float* p = Pw + quad * PADK + kb * 8 + qc;
        qa[kb][0] = __float_as_uint(p[0]);
        qa[kb][1] = __float_as_uint(p[8 * PADK]);
        qa[kb][2] = __float_as_uint(p[4]);
        qa[kb][3] = __float_as_uint(p[8 * PADK + 4]);
    }

    float o[8][4] = {};
    float lsum0 = 0.f, lsum1 = 0.f;
    const int nt = 2 * qt + 2;

    for (int j = 0; j < nt; j++) {
        __syncthreads();     // prev-iter Ks/Vs readers done (covers Q stage too)
        const float* Kt = Kb + (size_t)j * 64 * D_;
        const float* Vt = Vb + (size_t)j * 64 * D_;
        for (int i = tid; i < 64 * 16; i += 256) {
            int r = i >> 4, c4 = (i & 15) << 2;
            float4 kv = *(const float4*)(Kt + (size_t)r * D_ + c4);
            float* dk = Ks + r * PADK + c4;
            dk[0] = __uint_as_float(tf32b(kv.x));
            dk[1] = __uint_as_float(tf32b(kv.y));
            dk[2] = __uint_as_float(tf32b(kv.z));
            dk[3] = __uint_as_float(tf32b(kv.w));
            float4 vv = *(const float4*)(Vt + (size_t)r * D_ + c4);
            float* dv = Vs + r * PADK + c4;
            dv[0] = __uint_as_float(tf32b(vv.x));
            dv[1] = __uint_as_float(tf32b(vv.y));
            dv[2] = __uint_as_float(tf32b(vv.z));
            dv[3] = __uint_as_float(tf32b(vv.w));
        }
        __syncthreads();

        // ---- S = Q @ K^T : per warp 16x64, m16n8k8 frags ----
        float s[8][4] = {};
        #pragma unroll
        for (int kb = 0; kb < 8; kb++)
            #pragma unroll
            for (int nb = 0; nb < 8; nb++) {
                const float* kp = Ks + (nb * 8 + quad) * PADK + kb * 8 + qc;
                mma_tf32(s[nb], qa[kb],
                         __float_as_uint(kp[0]), __float_as_uint(kp[4]));
            }

        // ---- softmax (no max-shift) + P -> per-warp SMEM (tf32) ----
        const bool maskt = (j >= nt - 2);
        const int rowrel0 = q0 + w * 16 + quad - 64 * j;
        #pragma unroll
        for (int nb = 0; nb < 8; nb++) {
            const int k0 = nb * 8 + 2 * qc;
            float p0 = ex2(s[nb][0]), p1 = ex2(s[nb][1]);
            float p2 = ex2(s[nb][2]), p3 = ex2(s[nb][3]);
            if (maskt) {
                if (k0 > rowrel0)         p0 = 0.f;
                if (k0 + 1 > rowrel0)     p1 = 0.f;
                if (k0 > rowrel0 + 8)     p2 = 0.f;
                if (k0 + 1 > rowrel0 + 8) p3 = 0.f;
            }
            lsum0 += p0 + p1;
            lsum1 += p2 + p3;
            float* pw0 = Pw + quad * PADK + k0;
            pw0[0] = __uint_as_float(tf32b(p0));
            pw0[1] = __uint_as_float(tf32b(p1));
            float* pw1 = Pw + (quad + 8) * PADK + k0;
            pw1[0] = __uint_as_float(tf32b(p2));
            pw1[1] = __uint_as_float(tf32b(p3));
        }
        __syncwarp();

        // ---- O += P @ V ----
        #pragma unroll
        for (int kb = 0; kb < 8; kb++) {
            uint32_t pa[4];
            const float* pp = Pw + quad * PADK + kb * 8 + qc;
            pa[0] = __float_as_uint(pp[0]);
            pa[1] = __float_as_uint(pp[8 * PADK]);
            pa[2] = __float_as_uint(pp[4]);
            pa[3] = __float_as_uint(pp[8 * PADK + 4]);
            #pragma unroll
            for (int nb = 0; nb < 8; nb++) {
                const float* vp = Vs + (kb * 8 + qc) * PADK + nb * 8 + quad;
                mma_tf32(o[nb], pa,
                         __float_as_uint(vp[0]), __float_as_uint(vp[4 * PADK]));
            }
        }
    }

    // ---- epilogue: row-sum across quad, normalize, write g_Y [B,T,C] ----
    lsum0 += __shfl_xor_sync(0xffffffffu, lsum0, 1);
    lsum0 += __shfl_xor_sync(0xffffffffu, lsum0, 2);
    lsum1 += __shfl_xor_sync(0xffffffffu, lsum1, 1);
    lsum1 += __shfl_xor_sync(0xffffffffu, lsum1, 2);
    const float inv0 = 1.f / lsum0, inv1 = 1.f / lsum1;

    const int b = bh >> 4, h = bh & 15;
    const int r0 = q0 + w * 16 + quad;
    float* y0 = g_Y + ((size_t)b * T_ + r0) * C_ + h * 64;
    float* y1 = y0 + 8 * C_;
    #pragma unroll
    for (int nb = 0; nb < 8; nb++) {
        const int c = nb * 8 + 2 * qc;
        *(float2*)(y0 + c) = make_float2(o[nb][0] * inv0, o[nb][1] * inv0);
        *(float2*)(y1 + c) = make_float2(o[nb][2] * inv1, o[nb][3] * inv1);
    }
}

// ---------------------------------------------------------------------------
extern "C" void kernel_launch(void* const* d_in, const int* in_sizes, int n_in,
                              void* d_out, int out_size) {
    (void)in_sizes; (void)n_in; (void)out_size;
    const float* x  = (const float*)d_in[0];
    const float* qU = (const float*)d_in[1];
    const float* qV = (const float*)d_in[2];
    const float* kU = (const float*)d_in[3];
    const float* kV = (const float*)d_in[4];
    const float* vU = (const float*)d_in[5];
    const float* vV = (const float*)d_in[6];
    const float* cU = (const float*)d_in[7];
    const float* cV = (const float*)d_in[8];
    float* out = (float*)d_out;

    const int smem_att = (2 * 64 * PADK + 8 * 16 * PADK) * 4;   // 69632 B
    static int cfg_done = 0;
    if (!cfg_done) {
        cudaFuncSetAttribute(k_attn_mma,
                             cudaFuncAttributeMaxDynamicSharedMemorySize,
                             smem_att);
        cfg_done = 1;
    }

    const dim3 thr(256);
    const dim3 g_gemm1(NT / 64);            // 128
    const dim3 g_gemm2(C_ / 64, NT / 64);   // 16 x 128
    const dim3 g_att(T_ / 128, B_ * H_);    // 16 x 64

    k_xv<<<g_gemm1, thr>>>(x, qV, 0);
    k_pu<<<g_gemm2, thr>>>(qU, nullptr, 0);
    k_xv<<<g_gemm1, thr>>>(x, kV, 0);
    k_pu<<<g_gemm2, thr>>>(kU, nullptr, 1);
    k_xv<<<g_gemm1, thr>>>(x, vV, 0);
    k_pu<<<g_gemm2, thr>>>(vU, nullptr, 2);
    k_attn_mma<<<g_att, thr, smem_att>>>();
    k_xv<<<g_gemm1, thr>>>(nullptr, cV, 1);
    k_pu<<<g_gemm2, thr>>>(cU, out, 3);
}

// round 4
// speedup vs baseline: 2.9349x; 1.5175x over previous
#include <cuda_runtime.h>
#include <cstdint>
#include <math.h>

#define B_ 4
#define T_ 2048
#define C_ 1024
#define H_ 16
#define D_ 64
#define R_ 64
#define NT 8192   // B*T

// ---------------- scratch (device globals; no allocation) ----------------
__device__ float g_W[256 * 1024];    // stacked scaled V-weights (tf32 bits)
__device__ float g_Wu[4 * 1024 * 64];// cvt'd U weights (tf32 bits)
__device__ float g_P[NT * 192];      // rank-space P for q,k,v (tf32 bits)
__device__ float g_P2[NT * 64];      // rank-space P for c-proj (tf32 bits)
__device__ float g_Q[NT * C_];       // [B,H,T,D] (tf32 bits, pre-scaled)
__device__ float g_K[NT * C_];
__device__ float g_V[NT * C_];
__device__ float g_Y[NT * C_];       // attention out [B,T,C] (tf32 bits)

// =================== portable tensor-core helpers (sm_80+) =================
__device__ __forceinline__ uint32_t tf32b(float x) {
    uint32_t u;
    asm("cvt.rna.tf32.f32 %0, %1;" : "=r"(u) : "f"(x));
    return u;
}
__device__ __forceinline__ float tf32f(float x) {
    return __uint_as_float(tf32b(x));
}
__device__ __forceinline__ float ex2(float x) {
    float y;
    asm("ex2.approx.f32 %0, %1;" : "=f"(y) : "f"(x));
    return y;
}
__device__ __forceinline__ void mma_tf32(float* d, const uint32_t* a,
                                         uint32_t b0, uint32_t b1) {
    asm volatile(
        "mma.sync.aligned.m16n8k8.row.col.f32.tf32.tf32.f32 "
        "{%0,%1,%2,%3}, {%4,%5,%6,%7}, {%8,%9}, {%0,%1,%2,%3};"
        : "+f"(d[0]), "+f"(d[1]), "+f"(d[2]), "+f"(d[3])
        : "r"(a[0]), "r"(a[1]), "r"(a[2]), "r"(a[3]), "r"(b0), "r"(b1));
}
__device__ __forceinline__ uint32_t smem_u32(const void* p) {
    uint32_t a;
    asm("{ .reg .u64 t; cvta.to.shared.u64 t, %1; cvt.u32.u64 %0, t; }"
        : "=r"(a) : "l"(p));
    return a;
}
__device__ __forceinline__ void cp16(uint32_t dst, const void* src) {
    asm volatile("cp.async.cg.shared.global [%0], [%1], 16;"
                 :: "r"(dst), "l"(src));
}
#define CP_COMMIT() asm volatile("cp.async.commit_group;" ::: "memory")
#define CP_WAIT(n)  asm volatile("cp.async.wait_group %0;" :: "n"(n) : "memory")

// ---------------------------------------------------------------------------
// K0: prep — build scaled/cvt'd weights.
//   g_W rows: [0,64) Vq*s*0.125*log2e, [64,128) Vk*s, [128,192) Vv*s,
//             [192,256) Vc*s.      g_Wu: cvt'd copies of qU,kU,vU,cU.
// ---------------------------------------------------------------------------
__global__ __launch_bounds__(256) void k_prep(
    const float* __restrict__ qU, const float* __restrict__ kU,
    const float* __restrict__ vU, const float* __restrict__ cU,
    const float* __restrict__ qV, const float* __restrict__ kV,
    const float* __restrict__ vV, const float* __restrict__ cV) {
    const int b = blockIdx.x, tid = threadIdx.x;
    if (b < 256) {
        const int grp = b >> 6, r = b & 63;
        const float* Vsrc = (grp == 0) ? qV : (grp == 1) ? kV
                          : (grp == 2) ? vV : cV;
        float sc = powf((float)(r + 1), -0.7f);
        if (grp == 0) sc *= 0.125f * 1.4426950408889634f;
        const int c = tid * 4;
        float4 v = *(const float4*)(Vsrc + (size_t)r * 1024 + c);
        float4 o = make_float4(tf32f(v.x * sc), tf32f(v.y * sc),
                               tf32f(v.z * sc), tf32f(v.w * sc));
        *(float4*)(g_W + (size_t)b * 1024 + c) = o;
    } else {
        const float* Us[4] = {qU, kU, vU, cU};
        const int base = (b - 256) * 1024 + tid * 4;
        const int w = base >> 16, off = base & 65535;
        float4 u = *(const float4*)(Us[w] + off);
        float4 o = make_float4(tf32f(u.x), tf32f(u.y), tf32f(u.z), tf32f(u.w));
        *(float4*)(g_Wu + base) = o;
    }
}

// ---------------------------------------------------------------------------
// K1: stage-1 GEMM  P[m, n] = A[m, :1024] @ W[wrow0+n, :1024]^T
// M-tile 64, N = NOUT (192 or 64). 8 warps: wm=w&1 (2x16 rows),
// wn=w>>1 (NOUT/4 cols). cp.async double-buffered K-chunks of 32.
// A truncated to tf32 by mma; W pre-cvt'd. Output stored cvt'd.
// ---------------------------------------------------------------------------
#define PAD1 36
template <int NOUT>
__global__ __launch_bounds__(256) void k_g1(const float* __restrict__ Ain,
                                            int useY, int wrow0,
                                            float* __restrict__ Pout) {
    extern __shared__ float sg1[];
    float* As = sg1;                        // [2][64][PAD1]
    float* Bs = sg1 + 2 * 64 * PAD1;        // [2][NOUT][PAD1]
    const float* A = useY ? g_Y : Ain;
    const int tid = threadIdx.x, w = tid >> 5, lane = tid & 31;
    const int quad = lane >> 2, qc = lane & 3;
    const int wm = w & 1, wn = w >> 1;
    const int m0 = blockIdx.x * 64;
    constexpr int NB = NOUT / 32;           // nb count per warp

    auto stage = [&](int ch, int buf) {
        const int k0 = ch * 32;
        float* Ab = As + buf * 64 * PAD1;
        float* Bb = Bs + buf * NOUT * PAD1;
        #pragma unroll
        for (int t = 0; t < 2; t++) {       // A: 512 cp16
            int idx = tid + t * 256;
            int r = idx >> 3, c = (idx & 7) * 4;
            cp16(smem_u32(Ab + r * PAD1 + c),
                 A + (size_t)(m0 + r) * 1024 + k0 + c);
        }
        #pragma unroll
        for (int t = 0; t < NOUT / 32; t++) {  // B: NOUT*8 cp16
            int idx = tid + t * 256;
            int n = idx >> 3, c = (idx & 7) * 4;
            cp16(smem_u32(Bb + n * PAD1 + c),
                 g_W + (size_t)(wrow0 + n) * 1024 + k0 + c);
        }
    };

    float acc[2][NB][4];
    #pragma unroll
    for (int mf = 0; mf < 2; mf++)
        #pragma unroll
        for (int nb = 0; nb < NB; nb++)
            #pragma unroll
            for (int i = 0; i < 4; i++) acc[mf][nb][i] = 0.f;

    stage(0, 0);
    CP_COMMIT();
    int buf = 0;
    for (int ch = 0; ch < 32; ch++) {
        if (ch < 31) { stage(ch + 1, buf ^ 1); CP_COMMIT(); CP_WAIT(1); }
        else         { CP_WAIT(0); }
        __syncthreads();
        const float* Ab = As + buf * 64 * PAD1;
        const float* Bb = Bs + buf * NOUT * PAD1;
        #pragma unroll
        for (int kb = 0; kb < 4; kb++) {
            uint32_t a[2][4];
            #pragma unroll
            for (int mf = 0; mf < 2; mf++) {
                const float* ap = Ab + (wm * 32 + mf * 16 + quad) * PAD1
                                + kb * 8 + qc;
                a[mf][0] = __float_as_uint(ap[0]);
                a[mf][1] = __float_as_uint(ap[8 * PAD1]);
                a[mf][2] = __float_as_uint(ap[4]);
                a[mf][3] = __float_as_uint(ap[8 * PAD1 + 4]);
            }
            #pragma unroll
            for (int nb = 0; nb < NB; nb++) {
                const float* bp = Bb + (wn * (NOUT / 4) + nb * 8 + quad) * PAD1
                                + kb * 8 + qc;
                uint32_t b0 = __float_as_uint(bp[0]);
                uint32_t b1 = __float_as_uint(bp[4]);
                mma_tf32(acc[0][nb], a[0], b0, b1);
                mma_tf32(acc[1][nb], a[1], b0, b1);
            }
        }
        __syncthreads();
        buf ^= 1;
    }

    #pragma unroll
    for (int mf = 0; mf < 2; mf++) {
        const int row = m0 + wm * 32 + mf * 16 + quad;
        #pragma unroll
        for (int nb = 0; nb < NB; nb++) {
            const int col = wn * (NOUT / 4) + nb * 8 + 2 * qc;
            float* p0 = Pout + (size_t)row * NOUT + col;
            *(float2*)p0 = make_float2(tf32f(acc[mf][nb][0]),
                                       tf32f(acc[mf][nb][1]));
            float* p1 = p0 + 8 * NOUT;
            *(float2*)p1 = make_float2(tf32f(acc[mf][nb][2]),
                                       tf32f(acc[mf][nb][3]));
        }
    }
}

// ---------------------------------------------------------------------------
// K2: stage-2 GEMM  y[m, n] = P[m, :64] @ U[n0+n, :64]^T
// M-tile 128 (8 warps x 16 rows), N-tile 128, K=64 single shot.
// sel 0/1/2 -> g_Q/K/V head-split cvt'd;  sel 3 -> outp flat fp32.
// ---------------------------------------------------------------------------
#define PADK 68
__global__ __launch_bounds__(256) void k_g2(const float* __restrict__ Pin,
                                            int ps,
                                            const float* __restrict__ Wu,
                                            int sel, float* __restrict__ outp) {
    extern __shared__ float sg2[];
    float* As = sg2;                  // [128][PADK]
    float* Bs = sg2 + 128 * PADK;     // [128][PADK]
    const int tid = threadIdx.x, w = tid >> 5, lane = tid & 31;
    const int quad = lane >> 2, qc = lane & 3;
    const int m0 = blockIdx.y * 128, n0 = blockIdx.x * 128;

    #pragma unroll
    for (int t = 0; t < 8; t++) {         // A: 2048 cp16
        int idx = tid + t * 256;
        int r = idx >> 4, c = (idx & 15) * 4;
        cp16(smem_u32(As + r * PADK + c),
             Pin + (size_t)(m0 + r) * ps + c);
    }
    #pragma unroll
    for (int t = 0; t < 8; t++) {         // B: 2048 cp16
        int idx = tid + t * 256;
        int n = idx >> 4, c = (idx & 15) * 4;
        cp16(smem_u32(Bs + n * PADK + c),
             Wu + (size_t)(n0 + n) * 64 + c);
    }
    CP_COMMIT();
    CP_WAIT(0);
    __syncthreads();

    float acc[16][4];
    #pragma unroll
    for (int nb = 0; nb < 16; nb++)
        #pragma unroll
        for (int i = 0; i < 4; i++) acc[nb][i] = 0.f;

    #pragma unroll
    for (int kb = 0; kb < 8; kb++) {
        uint32_t a[4];
        const float* ap = As + (w * 16 + quad) * PADK + kb * 8 + qc;
        a[0] = __float_as_uint(ap[0]);
        a[1] = __float_as_uint(ap[8 * PADK]);
        a[2] = __float_as_uint(ap[4]);
        a[3] = __float_as_uint(ap[8 * PADK + 4]);
        #pragma unroll
        for (int nb = 0; nb < 16; nb++) {
            const float* bp = Bs + (nb * 8 + quad) * PADK + kb * 8 + qc;
            mma_tf32(acc[nb], a, __float_as_uint(bp[0]),
                     __float_as_uint(bp[4]));
        }
    }

    const int row = m0 + w * 16 + quad;
    if (sel < 3) {
        float* dst = (sel == 0) ? g_Q : (sel == 1) ? g_K : g_V;
        const int b = row >> 11, t = row & (T_ - 1);
        #pragma unroll
        for (int nb = 0; nb < 16; nb++) {
            const int col = n0 + nb * 8 + 2 * qc;
            const int h = col >> 6, d = col & 63;
            float* p0 = dst + (((size_t)(b * H_ + h) * T_ + t) * D_) + d;
            *(float2*)p0 = make_float2(tf32f(acc[nb][0]), tf32f(acc[nb][1]));
            float* p1 = p0 + 8 * D_;
            *(float2*)p1 = make_float2(tf32f(acc[nb][2]), tf32f(acc[nb][3]));
        }
    } else {
        #pragma unroll
        for (int nb = 0; nb < 16; nb++) {
            const int col = n0 + nb * 8 + 2 * qc;
            float* p0 = outp + (size_t)row * C_ + col;
            *(float2*)p0 = make_float2(acc[nb][0], acc[nb][1]);
            float* p1 = p0 + 8 * C_;
            *(float2*)p1 = make_float2(acc[nb][2], acc[nb][3]);
        }
    }
}

// ---------------------------------------------------------------------------
// K3: causal flash attention, mma tf32, cp.async double-buffered K/V.
// 128 q-rows/CTA, 8 warps x 16 rows, 64-key tiles. Q pre-scaled+cvt'd,
// K/V pre-cvt'd => raw cp.async staging, no conversion pass.
// No online max (|S| << 1): O accumulates in regs, normalize once.
// ---------------------------------------------------------------------------
__global__ __launch_bounds__(256) void k_attn_mma() {
    extern __shared__ float sm[];
    float* Ksb = sm;                       // [2][64][PADK]
    float* Vsb = sm + 2 * 64 * PADK;       // [2][64][PADK]
    float* Pb  = sm + 4 * 64 * PADK;       // 8 x [16][PADK]
    const int tid = threadIdx.x, w = tid >> 5, lane = tid & 31;
    const int quad = lane >> 2, qc = lane & 3;
    const int bh = blockIdx.y;
    const int qt = gridDim.x - 1 - blockIdx.x;   // heavy tiles first
    const int q0 = qt * 128;
    const float* Qb = g_Q + (size_t)bh * T_ * D_;
    const float* Kb = g_K + (size_t)bh * T_ * D_;
    const float* Vb = g_V + (size_t)bh * T_ * D_;
    float* Pw = Pb + w * 16 * PADK;
    const int nt = 2 * qt + 2;

    auto stage = [&](int j, int buf) {
        const float* Kt = Kb + (size_t)j * 64 * D_;
        const float* Vt = Vb + (size_t)j * 64 * D_;
        float* Kd = Ksb + buf * 64 * PADK;
        float* Vd = Vsb + buf * 64 * PADK;
        #pragma unroll
        for (int t = 0; t < 4; t++) {
            int idx = tid + t * 256;
            int r = idx >> 4, c = (idx & 15) * 4;
            cp16(smem_u32(Kd + r * PADK + c), Kt + (size_t)r * D_ + c);
            cp16(smem_u32(Vd + r * PADK + c), Vt + (size_t)r * D_ + c);
        }
    };

    stage(0, 0);
    CP_COMMIT();

    // ---- stage this warp's 16 Q rows (already scaled+cvt'd) ----
    for (int i = lane; i < 16 * 16; i += 32) {
        int r = i >> 4, c4 = (i & 15) << 2;
        *(float4*)(Pw + r * PADK + c4) =
            *(const float4*)(Qb + (size_t)(q0 + w * 16 + r) * D_ + c4);
    }
    __syncwarp();
    uint32_t qa[8][4];
    #pragma unroll
    for (int kb = 0; kb < 8; kb++) {
        const float* p = Pw + quad * PADK + kb * 8 + qc;
        qa[kb][0] = __float_as_uint(p[0]);
        qa[kb][1] = __float_as_uint(p[8 * PADK]);
        qa[kb][2] = __float_as_uint(p[4]);
        qa[kb][3] = __float_as_uint(p[8 * PADK + 4]);
    }

    float o[8][4] = {};
    float lsum0 = 0.f, lsum1 = 0.f;
    int buf = 0;

    for (int j = 0; j < nt; j++) {
        if (j + 1 < nt) { stage(j + 1, buf ^ 1); CP_COMMIT(); CP_WAIT(1); }
        else            { CP_WAIT(0); }
        __syncthreads();
        const float* Ks = Ksb + buf * 64 * PADK;
        const float* Vs = Vsb + buf * 64 * PADK;

        // ---- S = Q @ K^T ----
        float s[8][4] = {};
        #pragma unroll
        for (int kb = 0; kb < 8; kb++)
            #pragma unroll
            for (int nb = 0; nb < 8; nb++) {
                const float* kp = Ks + (nb * 8 + quad) * PADK + kb * 8 + qc;
                mma_tf32(s[nb], qa[kb],
                         __float_as_uint(kp[0]), __float_as_uint(kp[4]));
            }

        // ---- softmax (no max-shift; ex2 since log2e folded into Q) ----
        const bool maskt = (j >= nt - 2);
        const int rowrel0 = q0 + w * 16 + quad - 64 * j;
        #pragma unroll
        for (int nb = 0; nb < 8; nb++) {
            const int k0 = nb * 8 + 2 * qc;
            float p0 = ex2(s[nb][0]), p1 = ex2(s[nb][1]);
            float p2 = ex2(s[nb][2]), p3 = ex2(s[nb][3]);
            if (maskt) {
                if (k0 > rowrel0)         p0 = 0.f;
                if (k0 + 1 > rowrel0)     p1 = 0.f;
                if (k0 > rowrel0 + 8)     p2 = 0.f;
                if (k0 + 1 > rowrel0 + 8) p3 = 0.f;
            }
            lsum0 += p0 + p1;
            lsum1 += p2 + p3;
            float* pw0 = Pw + quad * PADK + k0;
            pw0[0] = tf32f(p0);
            pw0[1] = tf32f(p1);
            float* pw1 = Pw + (quad + 8) * PADK + k0;
            pw1[0] = tf32f(p2);
            pw1[1] = tf32f(p3);
        }
        __syncwarp();

        // ---- O += P @ V ----
        #pragma unroll
        for (int kb = 0; kb < 8; kb++) {
            uint32_t pa[4];
            const float* pp = Pw + quad * PADK + kb * 8 + qc;
            pa[0] = __float_as_uint(pp[0]);
            pa[1] = __float_as_uint(pp[8 * PADK]);
            pa[2] = __float_as_uint(pp[4]);
            pa[3] = __float_as_uint(pp[8 * PADK + 4]);
            #pragma unroll
            for (int nb = 0; nb < 8; nb++) {
                const float* vp = Vs + (kb * 8 + qc) * PADK + nb * 8 + quad;
                mma_tf32(o[nb], pa,
                         __float_as_uint(vp[0]), __float_as_uint(vp[4 * PADK]));
            }
        }
        __syncthreads();
        buf ^= 1;
    }

    // ---- epilogue: row-sum across quad lanes, normalize, write g_Y ----
    lsum0 += __shfl_xor_sync(0xffffffffu, lsum0, 1);
    lsum0 += __shfl_xor_sync(0xffffffffu, lsum0, 2);
    lsum1 += __shfl_xor_sync(0xffffffffu, lsum1, 1);
    lsum1 += __shfl_xor_sync(0xffffffffu, lsum1, 2);
    const float inv0 = 1.f / lsum0, inv1 = 1.f / lsum1;

    const int b = bh >> 4, h = bh & 15;
    const int r0 = q0 + w * 16 + quad;
    float* y0 = g_Y + ((size_t)b * T_ + r0) * C_ + h * 64;
    float* y1 = y0 + 8 * C_;
    #pragma unroll
    for (int nb = 0; nb < 8; nb++) {
        const int c = nb * 8 + 2 * qc;
        *(float2*)(y0 + c) = make_float2(tf32f(o[nb][0] * inv0),
                                         tf32f(o[nb][1] * inv0));
        *(float2*)(y1 + c) = make_float2(tf32f(o[nb][2] * inv1),
                                         tf32f(o[nb][3] * inv1));
    }
}

// ---------------------------------------------------------------------------
extern "C" void kernel_launch(void* const* d_in, const int* in_sizes, int n_in,
                              void* d_out, int out_size) {
    (void)in_sizes; (void)n_in; (void)out_size;
    const float* x  = (const float*)d_in[0];
    const float* qU = (const float*)d_in[1];
    const float* qV = (const float*)d_in[2];
    const float* kU = (const float*)d_in[3];
    const float* kV = (const float*)d_in[4];
    const float* vU = (const float*)d_in[5];
    const float* vV = (const float*)d_in[6];
    const float* cU = (const float*)d_in[7];
    const float* cV = (const float*)d_in[8];
    float* out = (float*)d_out;

    const int sm_g1a = (2 * 64 * PAD1 + 2 * 192 * PAD1) * 4;   // 73728
    const int sm_g1b = (2 * 64 * PAD1 + 2 * 64 * PAD1) * 4;    // 36864
    const int sm_g2  = (2 * 128 * PADK) * 4;                   // 69632
    const int sm_att = (4 * 64 * PADK + 8 * 16 * PADK) * 4;    // 104448
    static int cfg_done = 0;
    if (!cfg_done) {
        cudaFuncSetAttribute(k_g1<192>,
            cudaFuncAttributeMaxDynamicSharedMemorySize, sm_g1a);
        cudaFuncSetAttribute(k_g1<64>,
            cudaFuncAttributeMaxDynamicSharedMemorySize, sm_g1b);
        cudaFuncSetAttribute(k_g2,
            cudaFuncAttributeMaxDynamicSharedMemorySize, sm_g2);
        cudaFuncSetAttribute(k_attn_mma,
            cudaFuncAttributeMaxDynamicSharedMemorySize, sm_att);
        cfg_done = 1;
    }

    const dim3 thr(256);
    const dim3 g_s2(C_ / 128, NT / 128);    // 8 x 64
    const dim3 g_att(T_ / 128, B_ * H_);    // 16 x 64

    float* pP; cudaGetSymbolAddress((void**)&pP, g_P);
    float* pP2; cudaGetSymbolAddress((void**)&pP2, g_P2);
    float* pWu; cudaGetSymbolAddress((void**)&pWu, g_Wu);

    k_prep<<<512, thr>>>(qU, kU, vU, cU, qV, kV, vV, cV);
    k_g1<192><<<NT / 64, thr, sm_g1a>>>(x, 0, 0, pP);
    k_g2<<<g_s2, thr, sm_g2>>>(pP + 0,   192, pWu + 0 * 65536, 0, nullptr);
    k_g2<<<g_s2, thr, sm_g2>>>(pP + 64,  192, pWu + 1 * 65536, 1, nullptr);
    k_g2<<<g_s2, thr, sm_g2>>>(pP + 128, 192, pWu + 2 * 65536, 2, nullptr);
    k_attn_mma<<<g_att, thr, sm_att>>>();
    k_g1<64><<<NT / 64, thr, sm_g1b>>>(nullptr, 1, 192, pP2);
    k_g2<<<g_s2, thr, sm_g2>>>(pP2, 64, pWu + 3 * 65536, 3, out);
}

// round 5
// speedup vs baseline: 5.5114x; 1.8779x over previous
#include <cuda_runtime.h>
#include <cuda_fp16.h>
#include <cstdint>
#include <math.h>

#define B_ 4
#define T_ 2048
#define C_ 1024
#define H_ 16
#define D_ 64
#define R_ 64
#define NT 8192   // B*T

// ---------------- scratch (device globals; no allocation) ----------------
__device__ __half g_xh[NT * C_];      // x converted to half
__device__ __half g_W[256 * 1024];    // stacked scaled V-weights (half)
__device__ __half g_Wu[4 * 1024 * 64];// U weights (half)
__device__ __half g_P[NT * 192];      // rank-space P for q,k,v
__device__ __half g_P2[NT * 64];      // rank-space P for c-proj
__device__ __half g_Qh[NT * C_];      // [B,H,T,D], pre-scaled by 0.125*log2e
__device__ __half g_Kh[NT * C_];
__device__ __half g_Vh[NT * C_];
__device__ __half g_Yh[NT * C_];      // attention out [B,T,C]

// =================== portable tensor-core helpers (sm_80+) =================
__device__ __forceinline__ float ex2(float x) {
    float y;
    asm("ex2.approx.f32 %0, %1;" : "=f"(y) : "f"(x));
    return y;
}
__device__ __forceinline__ void mma_f16(float* d, const uint32_t* a,
                                        uint32_t b0, uint32_t b1) {
    asm volatile(
        "mma.sync.aligned.m16n8k16.row.col.f32.f16.f16.f32 "
        "{%0,%1,%2,%3}, {%4,%5,%6,%7}, {%8,%9}, {%0,%1,%2,%3};"
        : "+f"(d[0]), "+f"(d[1]), "+f"(d[2]), "+f"(d[3])
        : "r"(a[0]), "r"(a[1]), "r"(a[2]), "r"(a[3]), "r"(b0), "r"(b1));
}
__device__ __forceinline__ uint32_t smem_u32(const void* p) {
    uint32_t a;
    asm("{ .reg .u64 t; cvta.to.shared.u64 t, %1; cvt.u32.u64 %0, t; }"
        : "=r"(a) : "l"(p));
    return a;
}
__device__ __forceinline__ void cp16(uint32_t dst, const void* src) {
    asm volatile("cp.async.cg.shared.global [%0], [%1], 16;"
                 :: "r"(dst), "l"(src));
}
#define CP_COMMIT() asm volatile("cp.async.commit_group;" ::: "memory")
#define CP_WAIT(n)  asm volatile("cp.async.wait_group %0;" :: "n"(n) : "memory")
#define LDSM4(r, a)                                                         \
    asm volatile("ldmatrix.sync.aligned.m8n8.x4.shared.b16 "                \
                 "{%0,%1,%2,%3}, [%4];"                                     \
                 : "=r"((r)[0]), "=r"((r)[1]), "=r"((r)[2]), "=r"((r)[3])   \
                 : "r"(a))
#define LDSM4T(r, a)                                                        \
    asm volatile("ldmatrix.sync.aligned.m8n8.x4.trans.shared.b16 "          \
                 "{%0,%1,%2,%3}, [%4];"                                     \
                 : "=r"((r)[0]), "=r"((r)[1]), "=r"((r)[2]), "=r"((r)[3])   \
                 : "r"(a))
__device__ __forceinline__ uint32_t pack_h2(float lo, float hi) {
    __half2 h = __floats2half2_rn(lo, hi);
    return *(uint32_t*)&h;
}

// ---------------------------------------------------------------------------
// K_cvt: x fp32 -> half
// ---------------------------------------------------------------------------
__global__ __launch_bounds__(256) void k_cvt(const float* __restrict__ x) {
    const int base = (blockIdx.x * 256 + threadIdx.x) * 16;
    #pragma unroll
    for (int g = 0; g < 4; g++) {
        float4 v = *(const float4*)(x + base + g * 4);
        __half2 h0 = __floats2half2_rn(v.x, v.y);
        __half2 h1 = __floats2half2_rn(v.z, v.w);
        *(__half2*)(g_xh + base + g * 4)     = h0;
        *(__half2*)(g_xh + base + g * 4 + 2) = h1;
    }
}

// ---------------------------------------------------------------------------
// K_prepW: W rows [0,64) Vq*s*0.125*log2e, [64,128) Vk*s, [128,192) Vv*s,
//          [192,256) Vc*s.
// ---------------------------------------------------------------------------
__global__ __launch_bounds__(256) void k_prepW(
    const float* __restrict__ qV, const float* __restrict__ kV,
    const float* __restrict__ vV, const float* __restrict__ cV) {
    const int b = blockIdx.x, tid = threadIdx.x;
    const int grp = b >> 6, r = b & 63;
    const float* Vsrc = (grp == 0) ? qV : (grp == 1) ? kV
                      : (grp == 2) ? vV : cV;
    float sc = powf((float)(r + 1), -0.7f);
    if (grp == 0) sc *= 0.125f * 1.4426950408889634f;
    const int c = tid * 4;
    float4 v = *(const float4*)(Vsrc + (size_t)r * 1024 + c);
    *(__half2*)(g_W + (size_t)b * 1024 + c)     = __floats2half2_rn(v.x * sc, v.y * sc);
    *(__half2*)(g_W + (size_t)b * 1024 + c + 2) = __floats2half2_rn(v.z * sc, v.w * sc);
}

// K_prepU: cvt qU,kU,vU,cU -> g_Wu (half)
__global__ __launch_bounds__(256) void k_prepU(
    const float* __restrict__ qU, const float* __restrict__ kU,
    const float* __restrict__ vU, const float* __restrict__ cU) {
    const float* Us[4] = {qU, kU, vU, cU};
    const int base = blockIdx.x * 1024 + threadIdx.x * 4;
    const int w = base >> 16, off = base & 65535;
    float4 u = *(const float4*)(Us[w] + off);
    *(__half2*)(g_Wu + base)     = __floats2half2_rn(u.x, u.y);
    *(__half2*)(g_Wu + base + 2) = __floats2half2_rn(u.z, u.w);
}

// ---------------------------------------------------------------------------
// K1: stage-1 GEMM  P[m,n] = A[m,:1024] @ W[wrow0+n,:1024]^T   (fp16 mma)
// M-tile 64. 8 warps: wm=w&1 (2x16 rows), wn=w>>1 (NOUT/4 cols).
// cp.async double-buffered K-chunks of 32 (kb<2 m16n8k16 steps).
// ---------------------------------------------------------------------------
#define PADH1 40   // halfs; 80B row stride
template <int NOUT>
__global__ __launch_bounds__(256) void k_g1(const __half* __restrict__ A,
                                            int wrow0,
                                            __half* __restrict__ Pout) {
    extern __shared__ __half sg1h[];
    __half* As = sg1h;                      // [2][64][PADH1]
    __half* Bs = sg1h + 2 * 64 * PADH1;     // [2][NOUT][PADH1]
    const int tid = threadIdx.x, w = tid >> 5, lane = tid & 31;
    const int quad = lane >> 2, qc = lane & 3;
    const int wm = w & 1, wn = w >> 1;
    const int m0 = blockIdx.x * 64;
    constexpr int NB = NOUT / 32;

    auto stage = [&](int ch, int buf) {
        const int k0 = ch * 32;
        __half* Ab = As + buf * 64 * PADH1;
        __half* Bb = Bs + buf * NOUT * PADH1;
        {   // A: 256 cp16
            int r = tid >> 2, c8 = (tid & 3) * 8;
            cp16(smem_u32(Ab + r * PADH1 + c8),
                 A + (size_t)(m0 + r) * 1024 + k0 + c8);
        }
        #pragma unroll
        for (int t = 0; t < NOUT / 64; t++) {  // B: NOUT*4 cp16
            int idx = tid + t * 256;
            int n = idx >> 2, c8 = (idx & 3) * 8;
            cp16(smem_u32(Bb + n * PADH1 + c8),
                 g_W + (size_t)(wrow0 + n) * 1024 + k0 + c8);
        }
    };

    float acc[2][NB][4];
    #pragma unroll
    for (int mf = 0; mf < 2; mf++)
        #pragma unroll
        for (int nb = 0; nb < NB; nb++)
            #pragma unroll
            for (int i = 0; i < 4; i++) acc[mf][nb][i] = 0.f;

    stage(0, 0);
    CP_COMMIT();
    int buf = 0;
    for (int ch = 0; ch < 32; ch++) {
        if (ch < 31) { stage(ch + 1, buf ^ 1); CP_COMMIT(); CP_WAIT(1); }
        else         { CP_WAIT(0); }
        __syncthreads();
        const __half* Ab = As + buf * 64 * PADH1;
        const __half* Bb = Bs + buf * NOUT * PADH1;
        #pragma unroll
        for (int kb = 0; kb < 2; kb++) {
            uint32_t a[2][4];
            #pragma unroll
            for (int mf = 0; mf < 2; mf++) {
                const __half* ap = Ab + (wm * 32 + mf * 16 + quad) * PADH1
                                 + kb * 16 + 2 * qc;
                a[mf][0] = *(const uint32_t*)(ap);
                a[mf][1] = *(const uint32_t*)(ap + 8 * PADH1);
                a[mf][2] = *(const uint32_t*)(ap + 8);
                a[mf][3] = *(const uint32_t*)(ap + 8 * PADH1 + 8);
            }
            #pragma unroll
            for (int nb = 0; nb < NB; nb++) {
                const __half* bp = Bb + (wn * (NOUT / 4) + nb * 8 + quad) * PADH1
                                 + kb * 16 + 2 * qc;
                uint32_t b0 = *(const uint32_t*)(bp);
                uint32_t b1 = *(const uint32_t*)(bp + 8);
                mma_f16(acc[0][nb], a[0], b0, b1);
                mma_f16(acc[1][nb], a[1], b0, b1);
            }
        }
        __syncthreads();
        buf ^= 1;
    }

    #pragma unroll
    for (int mf = 0; mf < 2; mf++) {
        const int row = m0 + wm * 32 + mf * 16 + quad;
        #pragma unroll
        for (int nb = 0; nb < NB; nb++) {
            const int col = wn * (NOUT / 4) + nb * 8 + 2 * qc;
            *(__half2*)(Pout + (size_t)row * NOUT + col) =
                __floats2half2_rn(acc[mf][nb][0], acc[mf][nb][1]);
            *(__half2*)(Pout + (size_t)(row + 8) * NOUT + col) =
                __floats2half2_rn(acc[mf][nb][2], acc[mf][nb][3]);
        }
    }
}

// ---------------------------------------------------------------------------
// K2: stage-2 GEMM  y[m,n] = P[m,:64] @ U[n0+n,:64]^T   (fp16 mma)
// M-tile 128 (8 warps x 16 rows), N-tile 128, K=64 (kb<4).
// mode 0: grid.z=3 -> q/k/v head-split half. mode 1: c-proj -> fp32 out.
// ---------------------------------------------------------------------------
#define PADH2 72   // halfs; 144B row stride
__global__ __launch_bounds__(256) void k_g2(const __half* __restrict__ Pbase,
                                            int ps,
                                            const __half* __restrict__ Wubase,
                                            int mode, float* __restrict__ outp) {
    extern __shared__ __half sg2h[];
    __half* As = sg2h;                 // [128][PADH2]
    __half* Bs = sg2h + 128 * PADH2;   // [128][PADH2]
    const int tid = threadIdx.x, w = tid >> 5, lane = tid & 31;
    const int quad = lane >> 2, qc = lane & 3;
    const int m0 = blockIdx.y * 128, n0 = blockIdx.x * 128;
    const int z = blockIdx.z;
    const __half* Pin = Pbase + (mode == 0 ? z * 64 : 0);
    const __half* Wu  = Wubase + (mode == 0 ? z * 65536 : 0);

    #pragma unroll
    for (int t = 0; t < 4; t++) {       // A: 1024 cp16
        int idx = tid + t * 256;
        int r = idx >> 3, c8 = (idx & 7) * 8;
        cp16(smem_u32(As + r * PADH2 + c8),
             Pin + (size_t)(m0 + r) * ps + c8);
    }
    #pragma unroll
    for (int t = 0; t < 4; t++) {       // B: 1024 cp16
        int idx = tid + t * 256;
        int n = idx >> 3, c8 = (idx & 7) * 8;
        cp16(smem_u32(Bs + n * PADH2 + c8),
             Wu + (size_t)(n0 + n) * 64 + c8);
    }
    CP_COMMIT();
    CP_WAIT(0);
    __syncthreads();

    float acc[16][4];
    #pragma unroll
    for (int nb = 0; nb < 16; nb++)
        #pragma unroll
        for (int i = 0; i < 4; i++) acc[nb][i] = 0.f;

    #pragma unroll
    for (int kb = 0; kb < 4; kb++) {
        uint32_t a[4];
        const __half* ap = As + (w * 16 + quad) * PADH2 + kb * 16 + 2 * qc;
        a[0] = *(const uint32_t*)(ap);
        a[1] = *(const uint32_t*)(ap + 8 * PADH2);
        a[2] = *(const uint32_t*)(ap + 8);
        a[3] = *(const uint32_t*)(ap + 8 * PADH2 + 8);
        #pragma unroll
        for (int nb = 0; nb < 16; nb++) {
            const __half* bp = Bs + (nb * 8 + quad) * PADH2 + kb * 16 + 2 * qc;
            mma_f16(acc[nb], a, *(const uint32_t*)(bp),
                    *(const uint32_t*)(bp + 8));
        }
    }

    const int row = m0 + w * 16 + quad;
    if (mode == 0) {
        __half* dst = (z == 0) ? g_Qh : (z == 1) ? g_Kh : g_Vh;
        const int b = row >> 11, t = row & (T_ - 1);
        #pragma unroll
        for (int nb = 0; nb < 16; nb++) {
            const int col = n0 + nb * 8 + 2 * qc;
            const int h = col >> 6, d = col & 63;
            __half* p0 = dst + (((size_t)(b * H_ + h) * T_ + t) * D_) + d;
            *(__half2*)p0 = __floats2half2_rn(acc[nb][0], acc[nb][1]);
            *(__half2*)(p0 + 8 * D_) = __floats2half2_rn(acc[nb][2], acc[nb][3]);
        }
    } else {
        #pragma unroll
        for (int nb = 0; nb < 16; nb++) {
            const int col = n0 + nb * 8 + 2 * qc;
            float* p0 = outp + (size_t)row * C_ + col;
            *(float2*)p0 = make_float2(acc[nb][0], acc[nb][1]);
            *(float2*)(p0 + 8 * C_) = make_float2(acc[nb][2], acc[nb][3]);
        }
    }
}

// ---------------------------------------------------------------------------
// K3: causal flash attention, fp16 mma m16n8k16 + ldmatrix.
// 128 q-rows/CTA, 8 warps x 16 rows, 64-key tiles, cp.async double buffer.
// P stays in registers: S C-frag == P A-frag layout for m16n8k16.
// No online max (|S| << 1); O in regs; normalize once.
// ---------------------------------------------------------------------------
#define PADA 72    // halfs; 144B stride
__global__ __launch_bounds__(256) void k_attn() {
    extern __shared__ __half sah[];
    __half* Qs  = sah;                      // [128][PADA]
    __half* Ksb = sah + 128 * PADA;         // [2][64][PADA]
    __half* Vsb = Ksb + 2 * 64 * PADA;      // [2][64][PADA]
    const int tid = threadIdx.x, w = tid >> 5, lane = tid & 31;
    const int quad = lane >> 2, qc = lane & 3;
    const int msel = lane >> 3, rsel = lane & 7;
    const int mrow_a = (msel & 1) * 8 + rsel;   // Q / V(trans) row part
    const int mcol_a = (msel >> 1) * 8;
    const int mrow_b = (msel >> 1) * 8 + rsel;  // K row part
    const int mcol_b = (msel & 1) * 8;
    const int bh = blockIdx.y;
    const int qt = gridDim.x - 1 - blockIdx.x;  // heavy tiles first
    const int q0 = qt * 128;
    const __half* Qb = g_Qh + (size_t)bh * T_ * D_;
    const __half* Kb = g_Kh + (size_t)bh * T_ * D_;
    const __half* Vb = g_Vh + (size_t)bh * T_ * D_;
    const int nt = 2 * qt + 2;

    auto stage = [&](int j, int buf) {
        const __half* Kt = Kb + (size_t)j * 64 * D_;
        const __half* Vt = Vb + (size_t)j * 64 * D_;
        __half* Kd = Ksb + buf * 64 * PADA;
        __half* Vd = Vsb + buf * 64 * PADA;
        #pragma unroll
        for (int t = 0; t < 2; t++) {
            int idx = tid + t * 256;
            int r = idx >> 3, c8 = (idx & 7) * 8;
            cp16(smem_u32(Kd + r * PADA + c8), Kt + (size_t)r * D_ + c8);
            cp16(smem_u32(Vd + r * PADA + c8), Vt + (size_t)r * D_ + c8);
        }
    };

    // Q tile + first K/V tile
    #pragma unroll
    for (int t = 0; t < 4; t++) {
        int idx = tid + t * 256;
        int r = idx >> 3, c8 = (idx & 7) * 8;
        cp16(smem_u32(Qs + r * PADA + c8), Qb + (size_t)(q0 + r) * D_ + c8);
    }
    stage(0, 0);
    CP_COMMIT();

    uint32_t qa[4][4];
    float o[8][4] = {};
    float lsum0 = 0.f, lsum1 = 0.f;
    int buf = 0;

    for (int j = 0; j < nt; j++) {
        if (j + 1 < nt) { stage(j + 1, buf ^ 1); CP_COMMIT(); CP_WAIT(1); }
        else            { CP_WAIT(0); }
        __syncthreads();
        const __half* Ks = Ksb + buf * 64 * PADA;
        const __half* Vs = Vsb + buf * 64 * PADA;

        if (j == 0) {       // Q a-frags (once; Qs is ready with group 0)
            #pragma unroll
            for (int kb = 0; kb < 4; kb++)
                LDSM4(qa[kb], smem_u32(Qs + (w * 16 + mrow_a) * PADA
                                       + kb * 16 + mcol_a));
        }

        // ---- S = Q @ K^T ----
        float s[8][4];
        #pragma unroll
        for (int nb = 0; nb < 8; nb++)
            #pragma unroll
            for (int i = 0; i < 4; i++) s[nb][i] = 0.f;
        #pragma unroll
        for (int kb = 0; kb < 4; kb++)
            #pragma unroll
            for (int nbp = 0; nbp < 4; nbp++) {
                uint32_t bf[4];
                LDSM4(bf, smem_u32(Ks + (nbp * 16 + mrow_b) * PADA
                                   + kb * 16 + mcol_b));
                mma_f16(s[2 * nbp],     qa[kb], bf[0], bf[1]);
                mma_f16(s[2 * nbp + 1], qa[kb], bf[2], bf[3]);
            }

        // ---- softmax (no max-shift; log2e folded into Q) ----
        const bool maskt = (j >= nt - 2);
        const int rowrel0 = q0 + w * 16 + quad - 64 * j;
        #pragma unroll
        for (int nb = 0; nb < 8; nb++) {
            const int k0 = nb * 8 + 2 * qc;
            float p0 = ex2(s[nb][0]), p1 = ex2(s[nb][1]);
            float p2 = ex2(s[nb][2]), p3 = ex2(s[nb][3]);
            if (maskt) {
                if (k0 > rowrel0)         p0 = 0.f;
                if (k0 + 1 > rowrel0)     p1 = 0.f;
                if (k0 > rowrel0 + 8)     p2 = 0.f;
                if (k0 + 1 > rowrel0 + 8) p3 = 0.f;
            }
            lsum0 += p0 + p1;
            lsum1 += p2 + p3;
            s[nb][0] = p0; s[nb][1] = p1; s[nb][2] = p2; s[nb][3] = p3;
        }

        // ---- O += P @ V  (P A-frags direct from C-frags) ----
        #pragma unroll
        for (int kb = 0; kb < 4; kb++) {
            uint32_t pa[4];
            pa[0] = pack_h2(s[2 * kb][0],     s[2 * kb][1]);
            pa[1] = pack_h2(s[2 * kb][2],     s[2 * kb][3]);
            pa[2] = pack_h2(s[2 * kb + 1][0], s[2 * kb + 1][1]);
            pa[3] = pack_h2(s[2 * kb + 1][2], s[2 * kb + 1][3]);
            #pragma unroll
            for (int nbp = 0; nbp < 4; nbp++) {
                uint32_t vf[4];
                LDSM4T(vf, smem_u32(Vs + (kb * 16 + mrow_a) * PADA
                                    + nbp * 16 + mcol_a));
                mma_f16(o[2 * nbp],     pa, vf[0], vf[1]);
                mma_f16(o[2 * nbp + 1], pa, vf[2], vf[3]);
            }
        }
        __syncthreads();
        buf ^= 1;
    }

    // ---- epilogue: reduce row-sums over quad lanes, normalize, write Y ----
    lsum0 += __shfl_xor_sync(0xffffffffu, lsum0, 1);
    lsum0 += __shfl_xor_sync(0xffffffffu, lsum0, 2);
    lsum1 += __shfl_xor_sync(0xffffffffu, lsum1, 1);
    lsum1 += __shfl_xor_sync(0xffffffffu, lsum1, 2);
    const float inv0 = 1.f / lsum0, inv1 = 1.f / lsum1;

    const int b = bh >> 4, h = bh & 15;
    const int r0 = q0 + w * 16 + quad;
    __half* y0 = g_Yh + ((size_t)b * T_ + r0) * C_ + h * 64;
    __half* y1 = y0 + 8 * C_;
    #pragma unroll
    for (int nb = 0; nb < 8; nb++) {
        const int c = nb * 8 + 2 * qc;
        *(__half2*)(y0 + c) = __floats2half2_rn(o[nb][0] * inv0,
                                                o[nb][1] * inv0);
        *(__half2*)(y1 + c) = __floats2half2_rn(o[nb][2] * inv1,
                                                o[nb][3] * inv1);
    }
}

// ---------------------------------------------------------------------------
extern "C" void kernel_launch(void* const* d_in, const int* in_sizes, int n_in,
                              void* d_out, int out_size) {
    (void)in_sizes; (void)n_in; (void)out_size;
    const float* x  = (const float*)d_in[0];
    const float* qU = (const float*)d_in[1];
    const float* qV = (const float*)d_in[2];
    const float* kU = (const float*)d_in[3];
    const float* kV = (const float*)d_in[4];
    const float* vU = (const float*)d_in[5];
    const float* vV = (const float*)d_in[6];
    const float* cU = (const float*)d_in[7];
    const float* cV = (const float*)d_in[8];
    float* out = (float*)d_out;

    const int sm_g1a = (2 * 64 * PADH1 + 2 * 192 * PADH1) * 2;   // 40960
    const int sm_g1b = (2 * 64 * PADH1 + 2 * 64 * PADH1) * 2;    // 20480
    const int sm_g2  = (2 * 128 * PADH2) * 2;                    // 36864
    const int sm_att = (128 * PADA + 4 * 64 * PADA) * 2;         // 55296
    static int cfg_done = 0;
    if (!cfg_done) {
        cudaFuncSetAttribute(k_g1<192>,
            cudaFuncAttributeMaxDynamicSharedMemorySize, sm_g1a);
        cudaFuncSetAttribute(k_g1<64>,
            cudaFuncAttributeMaxDynamicSharedMemorySize, sm_g1b);
        cudaFuncSetAttribute(k_g2,
            cudaFuncAttributeMaxDynamicSharedMemorySize, sm_g2);
        cudaFuncSetAttribute(k_attn,
            cudaFuncAttributeMaxDynamicSharedMemorySize, sm_att);
        cfg_done = 1;
    }

    const dim3 thr(256);
    const dim3 g_qkv(C_ / 128, NT / 128, 3);   // 8 x 64 x 3
    const dim3 g_c(C_ / 128, NT / 128, 1);
    const dim3 g_att(T_ / 128, B_ * H_);       // 16 x 64

    __half* pXh; cudaGetSymbolAddress((void**)&pXh, g_xh);
    __half* pYh; cudaGetSymbolAddress((void**)&pYh, g_Yh);
    __half* pP;  cudaGetSymbolAddress((void**)&pP,  g_P);
    __half* pP2; cudaGetSymbolAddress((void**)&pP2, g_P2);
    __half* pWu; cudaGetSymbolAddress((void**)&pWu, g_Wu);

    k_cvt<<<2048, thr>>>(x);                                   // 1
    k_prepW<<<256, thr>>>(qV, kV, vV, cV);                     // 2
    k_prepU<<<256, thr>>>(qU, kU, vU, cU);                     // 3
    k_g1<192><<<NT / 64, thr, sm_g1a>>>(pXh, 0, pP);           // 4
    k_g2<<<g_qkv, thr, sm_g2>>>(pP, 192, pWu, 0, nullptr);     // 5
    k_attn<<<g_att, thr, sm_att>>>();                          // 6  (ncu -s 5)
    k_g1<64><<<NT / 64, thr, sm_g1b>>>(pYh, 192, pP2);         // 7
    k_g2<<<g_c, thr, sm_g2>>>(pP2, 64, pWu + 3 * 65536, 1, out); // 8
}